// round 4
// baseline (speedup 1.0000x reference)
#include <cuda_runtime.h>
#include <math.h>

// Problem shape (fixed by the dataset)
#define BDIM     4
#define SDIM     4096
#define HDIM     4096
#define EDIM     64
#define M_TOTAL  (BDIM * SDIM)      // 16384 rows

// Tiling
#define BM        128               // rows per CTA
#define KT        32                // K-tile
#define NT        (HDIM / KT)       // 128 K-tiles
#define XS_STRIDE 132               // (BM + 4) : multiple of 4 for 16B-aligned LDS.128
#define WS_STRIDE 68                // (EDIM + 4): multiple of 4 for aligned float4 LDS
#define NTHREADS  256

__global__ __launch_bounds__(NTHREADS, 1)
void router_kernel(const float* __restrict__ x,
                   const float* __restrict__ w,
                   float* __restrict__ out)
{
    // Union: GEMM tiles during mainloop, logits tile during epilogue.
    __shared__ union {
        struct {
            float xs[KT][XS_STRIDE];   // transposed: xs[kk][row]
            float ws[KT][WS_STRIDE];   // transposed: ws[kk][expert]
        } t;
        float ls[BM][EDIM + 1];        // logits for top-k scan
    } sm;

    const int tid = threadIdx.x;
    const int m0  = blockIdx.x * BM;

    // compute mapping: thread tile = 8 rows x 4 experts
    const int eg = tid & 15;           // experts 4*eg .. 4*eg+3
    const int rg = tid >> 4;           // rows    8*rg .. 8*rg+7

    // x global-load mapping: 4 float4 per thread per tile
    const int xk4   = tid & 7;         // float4 index in K within tile (0..7)
    const int xrow0 = tid >> 3;        // row 0..31, +32*i

    // w global-load mapping: 2 float4 per thread per tile
    const int wk4 = tid & 7;
    const int we0 = tid >> 3;          // expert 0..31, +32*i

    // accumulators: acc[row_pair][expert], each a packed f32x2 over (row, row+1)
    unsigned long long acc[4][4];
    #pragma unroll
    for (int i = 0; i < 4; i++)
        #pragma unroll
        for (int j = 0; j < 4; j++)
            acc[i][j] = 0ull;

    float4 xv[4], wv[2];

    // prefetch tile 0 into registers
    {
        const float* xp = x + (size_t)m0 * HDIM;
        #pragma unroll
        for (int i = 0; i < 4; i++)
            xv[i] = *(const float4*)(xp + (size_t)(xrow0 + 32 * i) * HDIM + 4 * xk4);
        #pragma unroll
        for (int i = 0; i < 2; i++)
            wv[i] = *(const float4*)(w + (size_t)(we0 + 32 * i) * HDIM + 4 * wk4);
    }

    for (int t = 0; t < NT; t++) {
        // store prefetched registers to smem (transposed)
        #pragma unroll
        for (int i = 0; i < 4; i++) {
            int row = xrow0 + 32 * i;
            sm.t.xs[4 * xk4 + 0][row] = xv[i].x;
            sm.t.xs[4 * xk4 + 1][row] = xv[i].y;
            sm.t.xs[4 * xk4 + 2][row] = xv[i].z;
            sm.t.xs[4 * xk4 + 3][row] = xv[i].w;
        }
        #pragma unroll
        for (int i = 0; i < 2; i++) {
            int e = we0 + 32 * i;
            sm.t.ws[4 * wk4 + 0][e] = wv[i].x;
            sm.t.ws[4 * wk4 + 1][e] = wv[i].y;
            sm.t.ws[4 * wk4 + 2][e] = wv[i].z;
            sm.t.ws[4 * wk4 + 3][e] = wv[i].w;
        }
        __syncthreads();

        // prefetch next tile (overlaps with compute below)
        if (t + 1 < NT) {
            const int k0 = (t + 1) * KT;
            const float* xp = x + (size_t)m0 * HDIM + k0;
            #pragma unroll
            for (int i = 0; i < 4; i++)
                xv[i] = *(const float4*)(xp + (size_t)(xrow0 + 32 * i) * HDIM + 4 * xk4);
            #pragma unroll
            for (int i = 0; i < 2; i++)
                wv[i] = *(const float4*)(w + (size_t)(we0 + 32 * i) * HDIM + k0 + 4 * wk4);
        }

        // mainloop: 32 kk steps, 16 fma.rn.f32x2 each
        #pragma unroll
        for (int kk = 0; kk < KT; kk++) {
            // LDS.128 on transposed x gives row-pair f32x2 operands for free
            ulonglong2 xa = *(const ulonglong2*)&sm.t.xs[kk][8 * rg];
            ulonglong2 xb = *(const ulonglong2*)&sm.t.xs[kk][8 * rg + 4];
            float4 wf = *(const float4*)&sm.t.ws[kk][4 * eg];

            unsigned long long xr[4];
            xr[0] = xa.x; xr[1] = xa.y; xr[2] = xb.x; xr[3] = xb.y;

            unsigned long long wd[4];
            asm("mov.b64 %0, {%1,%1};" : "=l"(wd[0]) : "r"(__float_as_uint(wf.x)));
            asm("mov.b64 %0, {%1,%1};" : "=l"(wd[1]) : "r"(__float_as_uint(wf.y)));
            asm("mov.b64 %0, {%1,%1};" : "=l"(wd[2]) : "r"(__float_as_uint(wf.z)));
            asm("mov.b64 %0, {%1,%1};" : "=l"(wd[3]) : "r"(__float_as_uint(wf.w)));

            #pragma unroll
            for (int rp = 0; rp < 4; rp++)
                #pragma unroll
                for (int e = 0; e < 4; e++)
                    asm("fma.rn.f32x2 %0, %1, %2, %0;"
                        : "+l"(acc[rp][e])
                        : "l"(xr[rp]), "l"(wd[e]));
        }
        __syncthreads();
    }

    // ---- epilogue: write logits (global + smem), then top-2 + softmax ----
    float* logits_out = out;
    float* idx_out    = out + (size_t)M_TOTAL * EDIM;
    float* p_out      = idx_out + (size_t)M_TOTAL * 2;

    // last loop iteration ended with __syncthreads(): safe to repurpose smem
    #pragma unroll
    for (int rp = 0; rp < 4; rp++) {
        #pragma unroll
        for (int e = 0; e < 4; e++) {
            unsigned int lo, hi;
            asm("mov.b64 {%0,%1}, %2;" : "=r"(lo), "=r"(hi) : "l"(acc[rp][e]));
            float v0 = __uint_as_float(lo);
            float v1 = __uint_as_float(hi);
            int r0  = 8 * rg + 2 * rp;       // local row (v0 -> r0, v1 -> r0+1)
            int col = 4 * eg + e;
            sm.ls[r0][col]     = v0;
            sm.ls[r0 + 1][col] = v1;
            size_t m = (size_t)(m0 + r0);
            logits_out[m * EDIM + col]       = v0;
            logits_out[(m + 1) * EDIM + col] = v1;
        }
    }
    __syncthreads();

    // one thread per row: stable top-2 (ties -> lower index first, matching lax.top_k)
    if (tid < BM) {
        const int row = tid;
        float best = -INFINITY, sec = -INFINITY;
        int bi = 0, si = 0;
        #pragma unroll 8
        for (int i = 0; i < EDIM; i++) {
            float v = sm.ls[row][i];
            if (v > best) { sec = best; si = bi; best = v; bi = i; }
            else if (v > sec) { sec = v; si = i; }
        }
        // softmax over [best, sec] in f32: exactly (1, e^{sec-best}) / (1 + e^{sec-best})
        float tt = expf(sec - best);
        float inv = 1.0f / (1.0f + tt);
        size_t m = (size_t)(m0 + row);
        idx_out[m * 2 + 0] = (float)bi;
        idx_out[m * 2 + 1] = (float)si;
        p_out[m * 2 + 0]   = inv;
        p_out[m * 2 + 1]   = tt * inv;
    }
}

extern "C" void kernel_launch(void* const* d_in, const int* in_sizes, int n_in,
                              void* d_out, int out_size)
{
    const float* x  = (const float*)d_in[0];
    const float* gw = (const float*)d_in[1];
    // defensive: identify tensors by size (x = 67108864, gate_w = 262144)
    if (n_in >= 2 && in_sizes[0] < in_sizes[1]) {
        const float* tmp = x; x = gw; gw = tmp;
    }
    router_kernel<<<M_TOTAL / BM, NTHREADS>>>(x, gw, (float*)d_out);
}